// round 2
// baseline (speedup 1.0000x reference)
#include <cuda_runtime.h>
#include <math.h>

#define D 50
#define E 300
#define KNB 63
#define NMAX 20000

// ---- device scratch (no allocations allowed) ----
__device__ float g_ent[NMAX * D];          // entity projection output
__device__ float g_node[NMAX * D];         // bilinear output
__device__ float g_Wt[D * D * 64];         // Wbil transposed: [c=(i*50+j)][o], o padded to 64
__device__ float g_WpT[E * 64];            // Wp transposed: [e][d], d padded to 64

// ============================================================
// Prep: transpose weights into coalesced [K][64] layouts
// ============================================================
__global__ void prep_kernel(const float* __restrict__ Wp,
                            const float* __restrict__ Wbil) {
    int idx = blockIdx.x * blockDim.x + threadIdx.x;
    if (idx < E * 64) {
        int c = idx >> 6, o = idx & 63;
        g_WpT[idx] = (o < D) ? Wp[o * E + c] : 0.f;
    }
    if (idx < D * D * 64) {
        int c = idx >> 6, o = idx & 63;
        g_Wt[idx] = (o < D) ? Wbil[o * D * D + c] : 0.f;
    }
}

// ============================================================
// Kernel A: ent = entity_emb @ Wp^T + bp   [N,300] x [300,50]
// 64-node x 64-out block tile, 4x4 register microtile
// ============================================================
__global__ __launch_bounds__(256) void ent_proj_kernel(
    const float* __restrict__ entity, const float* __restrict__ bp, int N) {
    __shared__ float As[64 * 50];
    __shared__ float Bs[50 * 64];
    int tid = threadIdx.x;
    int tx = tid & 15, ty = tid >> 4;   // 16x16 threads
    int n0 = blockIdx.x * 64;
    float acc[4][4] = {};

    for (int c0 = 0; c0 < E; c0 += 50) {
        __syncthreads();
        for (int idx = tid; idx < 64 * 50; idx += 256) {
            int n = idx / 50, c = idx % 50;
            As[idx] = (n0 + n < N) ? entity[(size_t)(n0 + n) * E + c0 + c] : 0.f;
        }
        for (int idx = tid; idx < 50 * 64; idx += 256)
            Bs[idx] = g_WpT[(size_t)c0 * 64 + idx];
        __syncthreads();
        #pragma unroll 10
        for (int c = 0; c < 50; c++) {
            float4 b = *(const float4*)&Bs[c * 64 + tx * 4];
            #pragma unroll
            for (int i = 0; i < 4; i++) {
                float a = As[(ty * 4 + i) * 50 + c];
                acc[i][0] += a * b.x; acc[i][1] += a * b.y;
                acc[i][2] += a * b.z; acc[i][3] += a * b.w;
            }
        }
    }
    #pragma unroll
    for (int i = 0; i < 4; i++) {
        int n = n0 + ty * 4 + i;
        if (n >= N) continue;
        #pragma unroll
        for (int jj = 0; jj < 4; jj++) {
            int o = tx * 4 + jj;
            if (o < D) g_ent[(size_t)n * D + o] = acc[i][jj] + bp[o];
        }
    }
}

// ============================================================
// Kernel B: bilinear node[n,o] = sum_{i,j} q[n,i] Wbil[o,i,j] ent[n,j] + bbil[o]
// Structured as GEMM [64 nodes, 2500] x [2500, 64] with A generated on the fly
// (A[n, i*50+j] = q[n,i]*ent[n,j]). Chunked over i (fixed i per chunk).
// Thread: 2 nodes x 8 outputs register tile.
// ============================================================
__global__ __launch_bounds__(256) void bilinear_kernel(
    const float* __restrict__ query, const float* __restrict__ bbil, int N) {
    __shared__ float qs[64 * 50];
    __shared__ float es[64 * 50];
    __shared__ float Bs[50 * 64];
    int tid = threadIdx.x;
    int tx = tid & 7;          // o = tx*8 .. tx*8+7
    int ty = tid >> 3;         // nodes ty*2, ty*2+1
    int n0 = blockIdx.x * 64;

    for (int idx = tid; idx < 64 * 50; idx += 256) {
        int n = idx / 50, x = idx % 50;
        int gn = n0 + n;
        float qv = 0.f, ev = 0.f;
        if (gn < N) {
            qv = query[(size_t)gn * D + x];
            ev = g_ent[(size_t)gn * D + x];
        }
        qs[idx] = qv;
        es[idx] = ev;
    }

    float acc[2][8] = {};
    int nA = ty * 2, nB = ty * 2 + 1;

    for (int i = 0; i < D; i++) {
        __syncthreads();
        for (int idx = tid; idx < 50 * 64; idx += 256)
            Bs[idx] = g_Wt[(size_t)i * (50 * 64) + idx];
        __syncthreads();
        float q0 = qs[nA * 50 + i];
        float q1 = qs[nB * 50 + i];
        #pragma unroll 10
        for (int j = 0; j < 50; j++) {
            float a0 = q0 * es[nA * 50 + j];
            float a1 = q1 * es[nB * 50 + j];
            float4 b0 = *(const float4*)&Bs[j * 64 + tx * 8];
            float4 b1 = *(const float4*)&Bs[j * 64 + tx * 8 + 4];
            acc[0][0] += a0 * b0.x; acc[0][1] += a0 * b0.y;
            acc[0][2] += a0 * b0.z; acc[0][3] += a0 * b0.w;
            acc[0][4] += a0 * b1.x; acc[0][5] += a0 * b1.y;
            acc[0][6] += a0 * b1.z; acc[0][7] += a0 * b1.w;
            acc[1][0] += a1 * b0.x; acc[1][1] += a1 * b0.y;
            acc[1][2] += a1 * b0.z; acc[1][3] += a1 * b0.w;
            acc[1][4] += a1 * b1.x; acc[1][5] += a1 * b1.y;
            acc[1][6] += a1 * b1.z; acc[1][7] += a1 * b1.w;
        }
    }

    int nn[2] = {nA, nB};
    #pragma unroll
    for (int ii = 0; ii < 2; ii++) {
        int n = n0 + nn[ii];
        if (n >= N) continue;
        #pragma unroll
        for (int jj = 0; jj < 8; jj++) {
            int o = tx * 8 + jj;
            if (o < D) g_node[(size_t)n * D + o] = acc[ii][jj] + bbil[o];
        }
    }
}

// ============================================================
// Kernel C: fused tail. Uses linearity of the GRN:
//   s[n,:] = sum_k scores[n,k]*nb[n,k,:] + scores[n,63]*node[n,:]
//   feats  = elu(s @ Wg^T + g_bias)
//   out    = feats @ Wr^T + br
// 1 warp per node, 8 nodes per 256-thread block. float2 streaming.
// ============================================================
__global__ __launch_bounds__(256) void tail_kernel(
    const float* __restrict__ nbr, const float* __restrict__ scores,
    const float* __restrict__ Wg, const float* __restrict__ g_bias,
    const float* __restrict__ Wr, const float* __restrict__ br,
    float* __restrict__ out, int N) {
    __shared__ float Wgs[50 * 51];   // padded row 51 -> conflict-free column access
    __shared__ float Wrs[50];
    __shared__ float gbs[50];
    __shared__ float s_sm[8][50];
    int tid = threadIdx.x;

    for (int idx = tid; idx < 2500; idx += 256) {
        int o = idx / 50, d = idx % 50;
        Wgs[o * 51 + d] = Wg[idx];
    }
    if (tid < 50) { Wrs[tid] = Wr[tid]; gbs[tid] = g_bias[tid]; }
    __syncthreads();

    int warp = tid >> 5, lane = tid & 31;
    int n = blockIdx.x * 8 + warp;
    if (n >= N) return;

    const float* base = nbr + (size_t)n * KNB * D;
    const float* sc   = scores + (size_t)n * (KNB + 1);

    // phase 1: attention-weighted neighbor sum (memory bound, coalesced float2)
    if (lane < 25) {
        float wK = sc[KNB];
        float2 v = *(const float2*)&g_node[(size_t)n * D + 2 * lane];
        float sx = wK * v.x, sy = wK * v.y;
        #pragma unroll 9
        for (int k = 0; k < KNB; k++) {
            float w = sc[k];
            float2 u = *(const float2*)&base[k * D + 2 * lane];
            sx += w * u.x;
            sy += w * u.y;
        }
        s_sm[warp][2 * lane]     = sx;
        s_sm[warp][2 * lane + 1] = sy;
    }
    __syncwarp();

    // phase 2: Wg projection + ELU + rank head, warp-reduced
    float r = 0.f;
    #pragma unroll
    for (int rep = 0; rep < 2; rep++) {
        int o = lane + 32 * rep;
        if (o < D) {
            float a = gbs[o];
            #pragma unroll 10
            for (int d = 0; d < D; d++)
                a += s_sm[warp][d] * Wgs[o * 51 + d];
            float f = (a > 0.f) ? a : expm1f(a);
            r += f * Wrs[o];
        }
    }
    #pragma unroll
    for (int off = 16; off; off >>= 1)
        r += __shfl_down_sync(0xffffffffu, r, off);
    if (lane == 0) out[n] = r + br[0];
}

// ============================================================
extern "C" void kernel_launch(void* const* d_in, const int* in_sizes, int n_in,
                              void* d_out, int out_size) {
    const float* query  = (const float*)d_in[0];
    const float* entity = (const float*)d_in[1];
    const float* nbr    = (const float*)d_in[2];
    const float* scores = (const float*)d_in[3];
    const float* Wp     = (const float*)d_in[4];
    const float* bp     = (const float*)d_in[5];
    const float* Wbil   = (const float*)d_in[6];
    const float* bbil   = (const float*)d_in[7];
    const float* Wg     = (const float*)d_in[8];
    const float* gbias  = (const float*)d_in[9];
    const float* Wr     = (const float*)d_in[10];
    const float* br     = (const float*)d_in[11];
    float* out = (float*)d_out;

    int N = in_sizes[0] / D;
    if (N > NMAX) N = NMAX;

    prep_kernel<<<(D * D * 64 + 255) / 256, 256>>>(Wp, Wbil);
    ent_proj_kernel<<<(N + 63) / 64, 256>>>(entity, bp, N);
    bilinear_kernel<<<(N + 63) / 64, 256>>>(query, bbil, N);
    tail_kernel<<<(N + 7) / 8, 256>>>(nbr, scores, Wg, gbias, Wr, br, out, N);
}

// round 3
// speedup vs baseline: 1.3557x; 1.3557x over previous
#include <cuda_runtime.h>
#include <math.h>

#define D 50
#define E 300
#define KNB 63
#define NMAX 20000
#define BROW 80   // padded B row: 4 og-groups * 20 floats (16 data + 4 pad)

// ---- device scratch ----
__device__ float g_ent[NMAX * D];
__device__ float g_node[NMAX * D];
__device__ float g_Wt2[D * D * BROW];   // [(i*50+j)][80] : og*20+c -> o=og*16+c
__device__ float g_WpT2[E * BROW];      // [k][80]

// ---- f32x2 helpers ----
__device__ __forceinline__ void fma2(unsigned long long& acc,
                                     unsigned long long a,
                                     unsigned long long b) {
    asm("fma.rn.f32x2 %0, %1, %2, %0;" : "+l"(acc) : "l"(a), "l"(b));
}
__device__ __forceinline__ unsigned long long dup2(float x) {
    unsigned long long r;
    asm("mov.b64 %0, {%1, %1};" : "=l"(r) : "f"(x));
    return r;
}
__device__ __forceinline__ float2 unpack2(unsigned long long v) {
    float2 r;
    asm("mov.b64 {%0, %1}, %2;" : "=f"(r.x), "=f"(r.y) : "l"(v));
    return r;
}

// ============================================================
// Prep: pad/transpose weights into [row][80] og-grouped layout
// ============================================================
__global__ void prep_kernel(const float* __restrict__ Wp,
                            const float* __restrict__ Wbil) {
    int idx = blockIdx.x * blockDim.x + threadIdx.x;
    if (idx < D * D * BROW) {
        int r = idx / BROW, col = idx % BROW;
        int og = col / 20, cc = col % 20;
        int o = og * 16 + cc;
        int i = r / D, j = r % D;
        g_Wt2[idx] = (cc < 16 && o < D) ? Wbil[o * (D * D) + i * D + j] : 0.f;
    }
    if (idx < E * BROW) {
        int k = idx / BROW, col = idx % BROW;
        int og = col / 20, cc = col % 20;
        int o = og * 16 + cc;
        g_WpT2[idx] = (cc < 16 && o < D) ? Wp[o * E + k] : 0.f;
    }
}

// ============================================================
// Kernel A: ent = entity @ Wp^T + bp    (f32x2 packed)
// block: 64 nodes, 128 threads; thread: 2 nodes x 16 outputs
// ============================================================
__global__ __launch_bounds__(128) void ent_proj_kernel(
    const float* __restrict__ entity, const float* __restrict__ bp, int N) {
    __shared__ float As[50 * 66];      // transposed [k][node], pad 66
    __shared__ float Bs[50 * BROW];
    int tid = threadIdx.x;
    int ng = tid >> 2, og = tid & 3;   // node group (0..31), out group (0..3)
    int n0 = blockIdx.x * 64;

    unsigned long long acc[2][8];
    #pragma unroll
    for (int s = 0; s < 2; s++)
        #pragma unroll
        for (int p = 0; p < 8; p++) acc[s][p] = 0ull;

    for (int c0 = 0; c0 < E; c0 += 50) {
        __syncthreads();
        for (int idx = tid; idx < 64 * 50; idx += 128) {
            int n = idx / 50, k = idx % 50;
            int gn = n0 + n;
            As[k * 66 + n] = (gn < N) ? entity[(size_t)gn * E + c0 + k] : 0.f;
        }
        for (int idx = tid; idx < 50 * BROW; idx += 128)
            Bs[idx] = g_WpT2[(size_t)c0 * BROW + idx];
        __syncthreads();
        #pragma unroll 10
        for (int k = 0; k < 50; k++) {
            float2 ap = *(const float2*)&As[k * 66 + 2 * ng];
            unsigned long long aA = dup2(ap.x), aB = dup2(ap.y);
            const ulonglong2* bpp = (const ulonglong2*)&Bs[k * BROW + og * 20];
            ulonglong2 u0 = bpp[0], u1 = bpp[1], u2 = bpp[2], u3 = bpp[3];
            fma2(acc[0][0], aA, u0.x); fma2(acc[0][1], aA, u0.y);
            fma2(acc[0][2], aA, u1.x); fma2(acc[0][3], aA, u1.y);
            fma2(acc[0][4], aA, u2.x); fma2(acc[0][5], aA, u2.y);
            fma2(acc[0][6], aA, u3.x); fma2(acc[0][7], aA, u3.y);
            fma2(acc[1][0], aB, u0.x); fma2(acc[1][1], aB, u0.y);
            fma2(acc[1][2], aB, u1.x); fma2(acc[1][3], aB, u1.y);
            fma2(acc[1][4], aB, u2.x); fma2(acc[1][5], aB, u2.y);
            fma2(acc[1][6], aB, u3.x); fma2(acc[1][7], aB, u3.y);
        }
    }
    #pragma unroll
    for (int s = 0; s < 2; s++) {
        int n = n0 + 2 * ng + s;
        if (n >= N) continue;
        #pragma unroll
        for (int p = 0; p < 8; p++) {
            int o = og * 16 + 2 * p;
            float2 v = unpack2(acc[s][p]);
            if (o < D)     g_ent[(size_t)n * D + o]     = v.x + bp[o];
            if (o + 1 < D) g_ent[(size_t)n * D + o + 1] = v.y + bp[o + 1];
        }
    }
}

// ============================================================
// Kernel B: bilinear node[n,o] = sum_ij q[n,i] Wbil[o,i,j] ent[n,j] + bbil
// GEMM with A generated on the fly; f32x2 packed accumulators.
// block: 64 nodes, 128 threads; thread: 2 nodes x 16 outputs
// ============================================================
__global__ __launch_bounds__(128) void bilinear_kernel(
    const float* __restrict__ query, const float* __restrict__ bbil, int N) {
    __shared__ float qs[50 * 66];
    __shared__ float es[50 * 66];
    __shared__ float Bs[50 * BROW];
    int tid = threadIdx.x;
    int ng = tid >> 2, og = tid & 3;
    int n0 = blockIdx.x * 64;

    for (int idx = tid; idx < 64 * 50; idx += 128) {
        int n = idx / 50, x = idx % 50;
        int gn = n0 + n;
        float qv = 0.f, ev = 0.f;
        if (gn < N) {
            qv = query[(size_t)gn * D + x];
            ev = g_ent[(size_t)gn * D + x];
        }
        qs[x * 66 + n] = qv;
        es[x * 66 + n] = ev;
    }

    unsigned long long acc[2][8];
    #pragma unroll
    for (int s = 0; s < 2; s++)
        #pragma unroll
        for (int p = 0; p < 8; p++) acc[s][p] = 0ull;

    for (int i = 0; i < D; i++) {
        __syncthreads();
        const float* src = g_Wt2 + (size_t)(i * D) * BROW;
        for (int idx = tid; idx < 50 * BROW; idx += 128)
            Bs[idx] = src[idx];
        __syncthreads();
        float2 qp = *(const float2*)&qs[i * 66 + 2 * ng];
        #pragma unroll 10
        for (int j = 0; j < 50; j++) {
            float2 ep = *(const float2*)&es[j * 66 + 2 * ng];
            unsigned long long aA = dup2(qp.x * ep.x);
            unsigned long long aB = dup2(qp.y * ep.y);
            const ulonglong2* bpp = (const ulonglong2*)&Bs[j * BROW + og * 20];
            ulonglong2 u0 = bpp[0], u1 = bpp[1], u2 = bpp[2], u3 = bpp[3];
            fma2(acc[0][0], aA, u0.x); fma2(acc[0][1], aA, u0.y);
            fma2(acc[0][2], aA, u1.x); fma2(acc[0][3], aA, u1.y);
            fma2(acc[0][4], aA, u2.x); fma2(acc[0][5], aA, u2.y);
            fma2(acc[0][6], aA, u3.x); fma2(acc[0][7], aA, u3.y);
            fma2(acc[1][0], aB, u0.x); fma2(acc[1][1], aB, u0.y);
            fma2(acc[1][2], aB, u1.x); fma2(acc[1][3], aB, u1.y);
            fma2(acc[1][4], aB, u2.x); fma2(acc[1][5], aB, u2.y);
            fma2(acc[1][6], aB, u3.x); fma2(acc[1][7], aB, u3.y);
        }
    }

    #pragma unroll
    for (int s = 0; s < 2; s++) {
        int n = n0 + 2 * ng + s;
        if (n >= N) continue;
        #pragma unroll
        for (int p = 0; p < 8; p++) {
            int o = og * 16 + 2 * p;
            float2 v = unpack2(acc[s][p]);
            if (o < D)     g_node[(size_t)n * D + o]     = v.x + bbil[o];
            if (o + 1 < D) g_node[(size_t)n * D + o + 1] = v.y + bbil[o + 1];
        }
    }
}

// ============================================================
// Kernel C: fused tail (linearity of GRN):
//   s[n] = sum_k sc[n,k]*nbr[n,k,:] + sc[n,63]*node[n,:]
//   out  = elu(s @ Wg^T + gb) @ Wr^T + br
// block: 10 nodes, 256 threads (25 threads/node in both phases)
// ============================================================
__global__ __launch_bounds__(256) void tail_kernel(
    const float* __restrict__ nbr, const float* __restrict__ scores,
    const float* __restrict__ Wg, const float* __restrict__ g_bias,
    const float* __restrict__ Wr, const float* __restrict__ br,
    float* __restrict__ out, int N) {
    __shared__ float Wgs[50 * 51];
    __shared__ float Wrs[50];
    __shared__ float gbs[50];
    __shared__ float s_sm[10][50];
    __shared__ float sc_sm[10][64];
    __shared__ float part[10][25];
    int tid = threadIdx.x;
    int nb = blockIdx.x * 10;

    for (int idx = tid; idx < 2500; idx += 256) {
        int o = idx / 50, d = idx % 50;
        Wgs[o * 51 + d] = Wg[idx];
    }
    if (tid < 50) { Wrs[tid] = Wr[tid]; gbs[tid] = g_bias[tid]; }
    for (int idx = tid; idx < 640; idx += 256) {
        int ln = idx >> 6, c = idx & 63;
        int n = nb + ln;
        sc_sm[ln][c] = (n < N) ? scores[(size_t)n * (KNB + 1) + c] : 0.f;
    }
    __syncthreads();

    int tn = tid / 25, tc = tid % 25;   // valid for tid < 250
    bool act = (tid < 250) && (nb + tn < N);

    if (act) {
        int n = nb + tn;
        const float* base = nbr + (size_t)n * (KNB * D) + 2 * tc;
        float s0 = 0.f, s1 = 0.f, t0 = 0.f, t1 = 0.f;
        #pragma unroll 4
        for (int k = 0; k < 62; k += 2) {
            float w0 = sc_sm[tn][k], w1 = sc_sm[tn][k + 1];
            float2 u0 = *(const float2*)(base + (size_t)k * D);
            float2 u1 = *(const float2*)(base + (size_t)(k + 1) * D);
            s0 += w0 * u0.x; s1 += w0 * u0.y;
            t0 += w1 * u1.x; t1 += w1 * u1.y;
        }
        {
            float w = sc_sm[tn][62];
            float2 u = *(const float2*)(base + (size_t)62 * D);
            s0 += w * u.x; s1 += w * u.y;
        }
        {
            float w = sc_sm[tn][KNB];
            float2 v = *(const float2*)&g_node[(size_t)n * D + 2 * tc];
            t0 += w * v.x; t1 += w * v.y;
        }
        s_sm[tn][2 * tc]     = s0 + t0;
        s_sm[tn][2 * tc + 1] = s1 + t1;
    }
    __syncthreads();

    if (act) {
        float rsum = 0.f;
        #pragma unroll
        for (int rep = 0; rep < 2; rep++) {
            int o = tc + 25 * rep;
            float a = gbs[o];
            #pragma unroll 10
            for (int d = 0; d < 50; d++)
                a += s_sm[tn][d] * Wgs[o * 51 + d];
            float f = (a > 0.f) ? a : expm1f(a);
            rsum += f * Wrs[o];
        }
        part[tn][tc] = rsum;
    }
    __syncthreads();

    if (tid < 10 && nb + tid < N) {
        float r = 0.f;
        #pragma unroll
        for (int c = 0; c < 25; c++) r += part[tid][c];
        out[nb + tid] = r + br[0];
    }
}

// ============================================================
extern "C" void kernel_launch(void* const* d_in, const int* in_sizes, int n_in,
                              void* d_out, int out_size) {
    const float* query  = (const float*)d_in[0];
    const float* entity = (const float*)d_in[1];
    const float* nbr    = (const float*)d_in[2];
    const float* scores = (const float*)d_in[3];
    const float* Wp     = (const float*)d_in[4];
    const float* bp     = (const float*)d_in[5];
    const float* Wbil   = (const float*)d_in[6];
    const float* bbil   = (const float*)d_in[7];
    const float* Wg     = (const float*)d_in[8];
    const float* gbias  = (const float*)d_in[9];
    const float* Wr     = (const float*)d_in[10];
    const float* br     = (const float*)d_in[11];
    float* out = (float*)d_out;

    int N = in_sizes[0] / D;
    if (N > NMAX) N = NMAX;

    prep_kernel<<<(D * D * BROW + 255) / 256, 256>>>(Wp, Wbil);
    ent_proj_kernel<<<(N + 63) / 64, 128>>>(entity, bp, N);
    bilinear_kernel<<<(N + 63) / 64, 128>>>(query, bbil, N);
    tail_kernel<<<(N + 9) / 10, 256>>>(nbr, scores, Wg, gbias, Wr, br, out, N);
}